// round 1
// baseline (speedup 1.0000x reference)
#include <cuda_runtime.h>
#include <cuda_bf16.h>

// Problem constants (fixed shapes for this dataset)
constexpr int Bn = 4096;
constexpr int Tn = 4096;
constexpr int NG = Tn / 4;     // float4 groups per row
constexpr int PF = 8;          // prefetch ring depth (groups); NG % PF == 0

__device__ __forceinline__ float battery_step(
    float s, float ga, float pa, float pp, float pr,
    float& cost_out, float& trace_out)
{
    const float C   = 13.5f;
    const float K   = 5.0f / 60.0f;     // KW_TO_KWH
    const float R   = 5.0f;             // MAX_CHARGE_RATE_KW

    // Off-critical-path precompute (depends only on inputs)
    float rp   = fminf(fmaxf(pa * pp, 0.0f), R);   // realised_pv_rate
    float p    = rp * K;                            // prov_pv_amount
    float agr  = ga * R;                            // attempted_grid_rate
    float gl   = fmaxf(agr, -R);                    // lower-clipped grid rate
    float pvk  = pp * K;
    float prc  = pr * 1.0e-3f;                      // price / 1000

    // Critical chain on s
    float after_pv = fminf(s + p, C);               // s>=0, p>=0 -> lower clip is a no-op
    float amt      = after_pv - s;                  // realised_pv_amt
    float hi       = R - amt * 12.0f;               // 5 - actual_pv_rate   (amt/K ~ amt*12)
    float rgr      = fminf(gl, hi);                 // realised_grid_rate
    float ns       = fminf(fmaxf(after_pv + rgr * K, 0.0f), C);

    // Outputs (off-chain)
    float grid_amt  = ns - after_pv;
    float pv_export = amt - pvk;
    cost_out  = prc * (grid_amt + pv_export);
    trace_out = ns;
    return ns;
}

__global__ void __launch_bounds__(32, 1) battery_kernel(
    const float* __restrict__ g_ga, const float* __restrict__ g_pa,
    const float* __restrict__ g_pp, const float* __restrict__ g_pr,
    float* __restrict__ g_trace, float* __restrict__ g_cost)
{
    const int b = blockIdx.x * 32 + threadIdx.x;   // one battery row per thread
    if (b >= Bn) return;

    const float4* gaR = reinterpret_cast<const float4*>(g_ga) + (size_t)b * NG;
    const float4* paR = reinterpret_cast<const float4*>(g_pa) + (size_t)b * NG;
    const float4* ppR = reinterpret_cast<const float4*>(g_pp) + (size_t)b * NG;
    const float4* prR = reinterpret_cast<const float4*>(g_pr) + (size_t)b * NG;
    float*  trR = g_trace + (size_t)b * (Tn + 1);
    float4* coR = reinterpret_cast<float4*>(g_cost) + (size_t)b * NG;

    // Register ring buffers: PF groups of 4 arrays x float4
    float4 bga[PF], bpa[PF], bpp[PF], bpr[PF];
#pragma unroll
    for (int j = 0; j < PF - 1; ++j) {
        bga[j] = gaR[j]; bpa[j] = paR[j]; bpp[j] = ppR[j]; bpr[j] = prR[j];
    }

    float s = 6.75f;                 // INITIAL_CHARGE_KWH
    trR[0] = s;

    for (int G0 = 0; G0 < NG; G0 += PF) {
#pragma unroll
        for (int j = 0; j < PF; ++j) {
            const int G  = G0 + j;
            const int pf = G + (PF - 1);           // group to prefetch now
            const int ps = (j + PF - 1) % PF;      // ring slot it lands in
            if (pf < NG) {
                bga[ps] = gaR[pf]; bpa[ps] = paR[pf];
                bpp[ps] = ppR[pf]; bpr[ps] = prR[pf];
            }
            const float4 vga = bga[j];
            const float4 vpa = bpa[j];
            const float4 vpp = bpp[j];
            const float4 vpr = bpr[j];

            float4 cst;
            float tr0, tr1, tr2, tr3;
            s = battery_step(s, vga.x, vpa.x, vpp.x, vpr.x, cst.x, tr0);
            s = battery_step(s, vga.y, vpa.y, vpp.y, vpr.y, cst.y, tr1);
            s = battery_step(s, vga.z, vpa.z, vpp.z, vpr.z, cst.z, tr2);
            s = battery_step(s, vga.w, vpa.w, vpp.w, vpr.w, cst.w, tr3);

            // trace row is shifted by 1 (trace[:,0] = init) -> scalar stores
            trR[4 * G + 1] = tr0;
            trR[4 * G + 2] = tr1;
            trR[4 * G + 3] = tr2;
            trR[4 * G + 4] = tr3;
            coR[G] = cst;
        }
    }
}

extern "C" void kernel_launch(void* const* d_in, const int* in_sizes, int n_in,
                              void* d_out, int out_size)
{
    const float* ga = (const float*)d_in[0];   // grid_action [B,T]
    const float* pa = (const float*)d_in[1];   // pv_action  [B,T]
    const float* pp = (const float*)d_in[2];   // pv_power   [B,T]
    const float* pr = (const float*)d_in[3];   // price      [B,T]

    float* out   = (float*)d_out;
    float* trace = out;                               // [B, T+1]
    float* cost  = out + (size_t)Bn * (Tn + 1);       // [B, T]

    battery_kernel<<<Bn / 32, 32>>>(ga, pa, pp, pr, trace, cost);
}